// round 9
// baseline (speedup 1.0000x reference)
#include <cuda_runtime.h>
#include <math.h>

#define N_SEQ 4096
#define SEQ_S 128
#define T_STEPS 127
#define VOCAB 36
#define E_DIM 128
#define H_DIM 256
#define G_DIM 1024            // 4*H
#define NH (N_SEQ * H_DIM)    // 1048576

static const size_t PROBS_OFF = (size_t)N_SEQ * T_STEPS * VOCAB;  // 18726912

// ---------------- scratch (device globals; no allocation allowed) ----------------
__device__ __align__(128) float g_h0[2][NH];                       // layer0 h ping-pong
__device__ __align__(128) float g_hz[NH];                          // zero h for t=0
__device__ __align__(128) float g_c0[NH];
__device__ __align__(128) float g_c1[NH];
__device__ __align__(128) float g_h1all[(size_t)T_STEPS * NH];     // layer1 h, all steps (533MB)
__device__ __align__(128) float g_Wcat0[G_DIM * 384];              // [W_ih0 | W_hh0], gate-permuted rows
__device__ __align__(128) float g_Wcat1[G_DIM * 512];              // [W_ih1 | W_hh1], gate-permuted rows
__device__ float g_bcat0[G_DIM];
__device__ float g_bcat1[G_DIM];
__device__ float g_acc[N_SEQ];                                     // masked NLL accumulator
__device__ float g_len[N_SEQ];

// ---------------- helpers ----------------
typedef unsigned long long ull;

__device__ __forceinline__ ull pack2(float x, float y) {
    ull r; asm("mov.b64 %0, {%1,%2};" : "=l"(r) : "f"(x), "f"(y)); return r;
}
__device__ __forceinline__ void unpack2(ull v, float& x, float& y) {
    asm("mov.b64 {%0,%1}, %2;" : "=f"(x), "=f"(y) : "l"(v));
}
// sm_103a packed fp32 FMA: d = a*b + d (per 32-bit lane)
__device__ __forceinline__ void ffma2(ull& d, ull a, ull b) {
    asm("fma.rn.f32x2 %0, %1, %2, %0;" : "+l"(d) : "l"(a), "l"(b));
}
__device__ __forceinline__ float sigmf(float v) { return 1.0f / (1.0f + expf(-v)); }

// ---------------- prep: permute gate rows into (i,f,g,o) quadruples, concat W_ih|W_hh ----------------
__global__ void prep_kernel(const float* __restrict__ W_ih0, const float* __restrict__ W_hh0,
                            const float* __restrict__ b_ih0, const float* __restrict__ b_hh0,
                            const float* __restrict__ W_ih1, const float* __restrict__ W_hh1,
                            const float* __restrict__ b_ih1, const float* __restrict__ b_hh1) {
    int jp = blockIdx.x;                 // permuted row 0..1023
    int gate = jp & 3, q = jp >> 2;
    int j = gate * H_DIM + q;            // original row
    int tid = threadIdx.x;               // 128 threads
    for (int k = tid; k < E_DIM; k += 128) g_Wcat0[jp * 384 + k] = W_ih0[j * E_DIM + k];
    for (int k = tid; k < H_DIM; k += 128) g_Wcat0[jp * 384 + E_DIM + k] = W_hh0[j * H_DIM + k];
    for (int k = tid; k < H_DIM; k += 128) g_Wcat1[jp * 512 + k] = W_ih1[j * H_DIM + k];
    for (int k = tid; k < H_DIM; k += 128) g_Wcat1[jp * 512 + H_DIM + k] = W_hh1[j * H_DIM + k];
    if (tid == 0) {
        g_bcat0[jp] = b_ih0[j] + b_hh0[j];
        g_bcat1[jp] = b_ih1[j] + b_hh1[j];
    }
}

// ---------------- init: zero state (re-done every launch; must be deterministic) ----------------
__global__ void init_kernel() {
    int i = blockIdx.x * blockDim.x + threadIdx.x;   // exactly NH threads
    g_hz[i] = 0.0f;
    g_c0[i] = 0.0f;
    g_c1[i] = 0.0f;
    if (i < N_SEQ) g_acc[i] = 0.0f;
}

// ---------------- lengths ----------------
__global__ void len_kernel(const int* __restrict__ x) {
    int n = blockIdx.x * 8 + (threadIdx.x >> 5);
    int lane = threadIdx.x & 31;
    int cnt = 0;
    for (int j = lane; j < SEQ_S; j += 32) cnt += (x[n * SEQ_S + j] != 0);
    for (int o = 16; o; o >>= 1) cnt += __shfl_down_sync(0xffffffffu, cnt, o);
    if (lane == 0) g_len[n] = (float)cnt;
}

// ---------------- fused LSTM step: gates GEMM (fp32x2 FFMA) + pointwise update ----------------
// Block tile: 128 sequences x 64 permuted gate cols (16 complete quadruples), K = KIN + 256.
// Thread (tx,ty): rows rowBase + ty*8 + {0..7}, cols colBase + tx*4 + {0..3} (one quadruple).
template <int KIN>
__global__ __launch_bounds__(256)
void lstm_step_kernel(const float* __restrict__ emb, const int* __restrict__ x, int t) {
    constexpr int KTOT = KIN + H_DIM;
    constexpr int NT = KTOT / 16;
    __shared__ float As[16][132];
    __shared__ float Bs[16][68];
    __shared__ int tokS[128];

    const float* inp; const float* hprev; float* hnew; float* cst;
    const float* Wc; const float* bc;
    if (KIN == E_DIM) {  // layer 0: input = embedding gather
        inp = emb;
        hprev = (t == 0) ? g_hz : g_h0[(t - 1) & 1];
        hnew = g_h0[t & 1];
        cst = g_c0; Wc = g_Wcat0; bc = g_bcat0;
    } else {             // layer 1: input = layer0 output of this step
        inp = g_h0[t & 1];
        hprev = (t == 0) ? g_hz : (g_h1all + (size_t)(t - 1) * NH);
        hnew = g_h1all + (size_t)t * NH;
        cst = g_c1; Wc = g_Wcat1; bc = g_bcat1;
    }

    const int rowBase = blockIdx.y * 128;
    const int colBase = blockIdx.x * 64;
    const int tid = threadIdx.x;
    const int tx = tid & 15, ty = tid >> 4;

    if (tid < 128)
        tokS[tid] = (KIN == E_DIM) ? x[(rowBase + tid) * SEQ_S + t] : (rowBase + tid);
    __syncthreads();

    float4 aR0, aR1, bR;

    auto loadA = [&](int kt, int s) -> float4 {
        int row = s >> 2, k4 = s & 3;
        int gk = kt * 16 + k4 * 4;
        const float* p = (gk < KIN)
            ? (inp + (size_t)tokS[row] * KIN + gk)
            : (hprev + (size_t)(rowBase + row) * H_DIM + (gk - KIN));
        return *(const float4*)p;
    };
    auto loadB = [&](int kt) -> float4 {
        int c = tid >> 2, k4 = tid & 3;
        return *(const float4*)(Wc + (size_t)(colBase + c) * KTOT + kt * 16 + k4 * 4);
    };
    auto storeT = [&]() {
        int r0 = tid >> 2, k4 = tid & 3;
        As[k4 * 4 + 0][r0] = aR0.x; As[k4 * 4 + 1][r0] = aR0.y;
        As[k4 * 4 + 2][r0] = aR0.z; As[k4 * 4 + 3][r0] = aR0.w;
        int r1 = r0 + 64;
        As[k4 * 4 + 0][r1] = aR1.x; As[k4 * 4 + 1][r1] = aR1.y;
        As[k4 * 4 + 2][r1] = aR1.z; As[k4 * 4 + 3][r1] = aR1.w;
        int c = tid >> 2;
        Bs[k4 * 4 + 0][c] = bR.x; Bs[k4 * 4 + 1][c] = bR.y;
        Bs[k4 * 4 + 2][c] = bR.z; Bs[k4 * 4 + 3][c] = bR.w;
    };

    ull acc[4][4];
#pragma unroll
    for (int u = 0; u < 4; u++)
#pragma unroll
        for (int j = 0; j < 4; j++) acc[u][j] = pack2(0.0f, 0.0f);

    aR0 = loadA(0, tid); aR1 = loadA(0, tid + 256); bR = loadB(0);
    storeT();
    __syncthreads();

    for (int kt = 0; kt < NT; kt++) {
        if (kt + 1 < NT) {
            aR0 = loadA(kt + 1, tid); aR1 = loadA(kt + 1, tid + 256); bR = loadB(kt + 1);
        }
#pragma unroll
        for (int k = 0; k < 16; k++) {
            ull ap0 = *(const ull*)&As[k][ty * 8 + 0];
            ull ap1 = *(const ull*)&As[k][ty * 8 + 2];
            ull ap2 = *(const ull*)&As[k][ty * 8 + 4];
            ull ap3 = *(const ull*)&As[k][ty * 8 + 6];
            float4 b4 = *(const float4*)&Bs[k][tx * 4];
            ull bp0 = pack2(b4.x, b4.x), bp1 = pack2(b4.y, b4.y);
            ull bp2 = pack2(b4.z, b4.z), bp3 = pack2(b4.w, b4.w);
            ffma2(acc[0][0], ap0, bp0); ffma2(acc[0][1], ap0, bp1);
            ffma2(acc[0][2], ap0, bp2); ffma2(acc[0][3], ap0, bp3);
            ffma2(acc[1][0], ap1, bp0); ffma2(acc[1][1], ap1, bp1);
            ffma2(acc[1][2], ap1, bp2); ffma2(acc[1][3], ap1, bp3);
            ffma2(acc[2][0], ap2, bp0); ffma2(acc[2][1], ap2, bp1);
            ffma2(acc[2][2], ap2, bp2); ffma2(acc[2][3], ap2, bp3);
            ffma2(acc[3][0], ap3, bp0); ffma2(acc[3][1], ap3, bp1);
            ffma2(acc[3][2], ap3, bp2); ffma2(acc[3][3], ap3, bp3);
        }
        __syncthreads();
        if (kt + 1 < NT) { storeT(); __syncthreads(); }
    }

    // pointwise LSTM update (this thread owns quadruple q for its 8 rows)
    float bi = bc[colBase + tx * 4 + 0];
    float bf = bc[colBase + tx * 4 + 1];
    float bg = bc[colBase + tx * 4 + 2];
    float bo = bc[colBase + tx * 4 + 3];
    int q = (colBase >> 2) + tx;
#pragma unroll
    for (int u = 0; u < 4; u++) {
        float gi0, gi1, gf0, gf1, gg0, gg1, go0, go1;
        unpack2(acc[u][0], gi0, gi1);
        unpack2(acc[u][1], gf0, gf1);
        unpack2(acc[u][2], gg0, gg1);
        unpack2(acc[u][3], go0, go1);
        int r = rowBase + ty * 8 + 2 * u;
        {
            size_t ci = (size_t)r * H_DIM + q;
            float ii = sigmf(gi0 + bi), ff = sigmf(gf0 + bf);
            float gg = tanhf(gg0 + bg), oo = sigmf(go0 + bo);
            float cn = ff * cst[ci] + ii * gg;
            cst[ci] = cn;
            hnew[ci] = oo * tanhf(cn);
        }
        {
            size_t ci = (size_t)(r + 1) * H_DIM + q;
            float ii = sigmf(gi1 + bi), ff = sigmf(gf1 + bf);
            float gg = tanhf(gg1 + bg), oo = sigmf(go1 + bo);
            float cn = ff * cst[ci] + ii * gg;
            cst[ci] = cn;
            hnew[ci] = oo * tanhf(cn);
        }
    }
}

// ---------------- fc + relu + log_softmax + probs + masked NLL, for all (n,t) ----------------
// Block: 8 sequences x 36 vocab = 288 threads; grid (N/8, T)
__global__ __launch_bounds__(288)
void fc_kernel(const float* __restrict__ fc_W, const float* __restrict__ fc_b,
               const int* __restrict__ x, float* __restrict__ out) {
    __shared__ float Ws[VOCAB][H_DIM + 1];   // 36*257*4 = 37KB
    __shared__ float hs[8][H_DIM];           // 8KB
    __shared__ float lg[8][VOCAB + 2];
    __shared__ float lse_s[8];

    const int t = blockIdx.y;
    const int n0 = blockIdx.x * 8;
    const int tid = threadIdx.x;

    for (int i = tid; i < VOCAB * H_DIM; i += 288) Ws[i / H_DIM][i % H_DIM] = fc_W[i];
    const float* hsrc = g_h1all + (size_t)t * NH + (size_t)n0 * H_DIM;
    for (int i = tid; i < 8 * H_DIM; i += 288) hs[i / H_DIM][i % H_DIM] = hsrc[i];
    __syncthreads();

    int s = tid / VOCAB;        // 0..7
    int v = tid - s * VOCAB;    // 0..35
    float a = fc_b[v];
#pragma unroll 8
    for (int k = 0; k < H_DIM; k++) a += hs[s][k] * Ws[v][k];
    float l = fmaxf(a, 0.0f);   // relu
    lg[s][v] = l;
    __syncthreads();

    if (v == 0) {
        float m = -1e30f;
        for (int j = 0; j < VOCAB; j++) m = fmaxf(m, lg[s][j]);
        float sum = 0.0f;
        for (int j = 0; j < VOCAB; j++) sum += expf(lg[s][j] - m);
        lse_s[s] = m + logf(sum);
    }
    __syncthreads();

    float lse = lse_s[s];
    int n = n0 + s;
    out[((size_t)n * T_STEPS + t) * VOCAB + v] = expf(l - lse);   // probs
    int tgt = x[n * SEQ_S + t + 1];
    if (v == tgt && tgt != 0) atomicAdd(&g_acc[n], lse - l);      // masked NLL
}

// ---------------- finalize: molecule_loss + mean loss ----------------
__global__ void finalize_kernel(float* __restrict__ out) {
    __shared__ float red[1024];
    int tid = threadIdx.x;
    float sum = 0.0f;
    for (int n = tid; n < N_SEQ; n += 1024) {
        float ml = g_acc[n] / g_len[n];
        out[PROBS_OFF + n] = ml;
        sum += ml;
    }
    red[tid] = sum;
    __syncthreads();
    for (int sft = 512; sft > 0; sft >>= 1) {
        if (tid < sft) red[tid] += red[tid + sft];
        __syncthreads();
    }
    if (tid == 0) out[PROBS_OFF + N_SEQ] = red[0] / (float)N_SEQ;
}

// ---------------- launch ----------------
extern "C" void kernel_launch(void* const* d_in, const int* in_sizes, int n_in,
                              void* d_out, int out_size) {
    const int*   x     = (const int*)  d_in[0];
    const float* emb   = (const float*)d_in[1];
    const float* W_ih0 = (const float*)d_in[2];
    const float* W_hh0 = (const float*)d_in[3];
    const float* b_ih0 = (const float*)d_in[4];
    const float* b_hh0 = (const float*)d_in[5];
    const float* W_ih1 = (const float*)d_in[6];
    const float* W_hh1 = (const float*)d_in[7];
    const float* b_ih1 = (const float*)d_in[8];
    const float* b_hh1 = (const float*)d_in[9];
    const float* fc_W  = (const float*)d_in[10];
    const float* fc_b  = (const float*)d_in[11];
    float* out = (float*)d_out;

    prep_kernel<<<G_DIM, 128>>>(W_ih0, W_hh0, b_ih0, b_hh0, W_ih1, W_hh1, b_ih1, b_hh1);
    init_kernel<<<NH / 256, 256>>>();
    len_kernel<<<N_SEQ / 8, 256>>>(x);

    dim3 grid(G_DIM / 64, N_SEQ / 128);   // 16 x 32 = 512 blocks
    for (int t = 0; t < T_STEPS; t++) {
        lstm_step_kernel<E_DIM><<<grid, 256>>>(emb, x, t);
        lstm_step_kernel<H_DIM><<<grid, 256>>>(emb, x, t);
    }

    fc_kernel<<<dim3(N_SEQ / 8, T_STEPS), 288>>>(fc_W, fc_b, x, out);
    finalize_kernel<<<1, 1024>>>(out);
}

// round 11
// speedup vs baseline: 2.1842x; 2.1842x over previous
#include <cuda_runtime.h>
#include <cuda_bf16.h>
#include <math.h>
#include <stdint.h>

#define N_SEQ 4096
#define SEQ_S 128
#define T_STEPS 127
#define VOCAB 36
#define E_DIM 128
#define H_DIM 256
#define G_DIM 1024
#define NH (N_SEQ * H_DIM)            // 1048576 = one full h-state (also 4 chunks * 32 blocks * 8192)
#define IMG_ELEMS 8192                 // 128 rows x 64 k, bf16 (16KB)
#define STAGE_BYTES 65536              // Ahi/Alo/Bhi/Blo images
#define SMEM_SZ 133120

static const size_t PROBS_OFF = (size_t)N_SEQ * T_STEPS * VOCAB;  // 18726912

// ---------------- device scratch (no allocations allowed) ----------------
__device__ __align__(128) __nv_bfloat16 g_W0hi[8 * 4 * IMG_ELEMS], g_W0lo[8 * 4 * IMG_ELEMS];
__device__ __align__(128) __nv_bfloat16 g_W1hi[8 * 8 * IMG_ELEMS], g_W1lo[8 * 8 * IMG_ELEMS];
__device__ __align__(128) __nv_bfloat16 g_h0hi[2 * NH], g_h0lo[2 * NH];   // swizzled image layout
__device__ __align__(128) __nv_bfloat16 g_h1hi[2 * NH], g_h1lo[2 * NH];
__device__ __align__(128) float g_h1f[(size_t)T_STEPS * NH];              // fp32 h1 history for fc
__device__ __align__(128) float g_projP[VOCAB * G_DIM];                   // emb@W_ih0^T + b, unit-major
__device__ __align__(128) float g_b1U[G_DIM];                             // layer1 bias, unit-major
__device__ __align__(128) float g_c0[NH], g_c1[NH];
__device__ float g_acc[N_SEQ], g_len[N_SEQ];

// ---------------- helpers ----------------
__device__ __forceinline__ unsigned smem_u32(const void* p) {
    unsigned a;
    asm("{ .reg .u64 t; cvta.to.shared.u64 t, %1; cvt.u32.u64 %0, t; }" : "=r"(a) : "l"(p));
    return a;
}
// element offset inside a 128x64 bf16 swizzled image (ldmatrix-friendly XOR swizzle)
__device__ __forceinline__ int img_off(int row, int kk) {
    return row * 64 + ((((kk >> 3) ^ (row & 7)) << 3) | (kk & 7));
}
__device__ __forceinline__ float fsig(float x) { return __fdividef(1.0f, 1.0f + __expf(-x)); }
__device__ __forceinline__ float ftanh(float x) { return __fdividef(2.0f, 1.0f + __expf(-2.0f * x)) - 1.0f; }

#define MBAR_INIT(addr, cnt) \
    asm volatile("mbarrier.init.shared.b64 [%0], %1;" :: "r"(addr), "r"(cnt) : "memory")
#define MBAR_EXPECT(addr, tx) \
    asm volatile("mbarrier.arrive.expect_tx.shared.b64 _, [%0], %1;" :: "r"(addr), "r"(tx) : "memory")
#define BULK_G2S(dst, src, bytes, mb) \
    asm volatile("cp.async.bulk.shared::cta.global.mbarrier::complete_tx::bytes [%0], [%1], %2, [%3];" \
                 :: "r"(dst), "l"(src), "r"(bytes), "r"(mb) : "memory")

__device__ __forceinline__ void mbar_wait(unsigned addr, unsigned parity) {
    unsigned done;
    asm volatile("{\n\t.reg .pred p;\n\t"
                 "mbarrier.try_wait.parity.acquire.cta.shared::cta.b64 p, [%1], %2;\n\t"
                 "selp.b32 %0, 1, 0, p;\n\t}" : "=r"(done) : "r"(addr), "r"(parity) : "memory");
    if (!done) {
        asm volatile("{\n\t.reg .pred P1;\n\t"
                     "WL_%=:\n\t"
                     "mbarrier.try_wait.parity.acquire.cta.shared::cta.b64 P1, [%0], %1, 0x989680;\n\t"
                     "@P1 bra.uni WD_%=;\n\t"
                     "bra.uni WL_%=;\n\t"
                     "WD_%=:\n\t}" :: "r"(addr), "r"(parity) : "memory");
    }
}

#define LDSM4(r0, r1, r2, r3, addr) \
    asm volatile("ldmatrix.sync.aligned.m8n8.x4.shared.b16 {%0,%1,%2,%3}, [%4];" \
                 : "=r"(r0), "=r"(r1), "=r"(r2), "=r"(r3) : "r"(addr))

#define MMA16816(d, a, b0, b1) \
    asm volatile("mma.sync.aligned.m16n8k16.row.col.f32.bf16.bf16.f32 " \
                 "{%0,%1,%2,%3}, {%4,%5,%6,%7}, {%8,%9}, {%0,%1,%2,%3};" \
                 : "+f"((d)[0]), "+f"((d)[1]), "+f"((d)[2]), "+f"((d)[3]) \
                 : "r"((a)[0]), "r"((a)[1]), "r"((a)[2]), "r"((a)[3]), "r"(b0), "r"(b1))

// ---------------- prep: permute + split weights into swizzled ldmatrix images ----------------
// permuted column for (gate, unit q): epilogue-register-local mapping
__device__ __forceinline__ int perm_nloc(int gate, int q, int& blockN) {
    blockN = q >> 5;
    int rem = q & 31, wcol = rem >> 4, rem2 = rem & 15, a = rem2 >> 2, jp = rem2 & 3;
    return wcol * 64 + 2 * a + 16 * jp + 8 * (gate >> 1) + (gate & 1);
}

__global__ void prep_w(const float* __restrict__ W_hh0,
                       const float* __restrict__ W_ih1, const float* __restrict__ W_hh1,
                       const float* __restrict__ b_ih1, const float* __restrict__ b_hh1) {
    int jo = blockIdx.x, tid = threadIdx.x;          // original gate row 0..1023
    int gate = jo >> 8, q = jo & 255;
    int bN;
    int nloc = perm_nloc(gate, q, bN);
    for (int k = tid; k < H_DIM; k += 128) {         // W0 = W_hh0 only (ih0 folded into proj)
        float v = W_hh0[jo * H_DIM + k];
        __nv_bfloat16 hi = __float2bfloat16(v);
        __nv_bfloat16 lo = __float2bfloat16(v - __bfloat162float(hi));
        int idx = (bN * 4 + (k >> 6)) * IMG_ELEMS + img_off(nloc, k & 63);
        g_W0hi[idx] = hi; g_W0lo[idx] = lo;
    }
    for (int k = tid; k < 512; k += 128) {           // W1 = [W_ih1 | W_hh1]
        float v = (k < H_DIM) ? W_ih1[jo * H_DIM + k] : W_hh1[jo * H_DIM + k - H_DIM];
        __nv_bfloat16 hi = __float2bfloat16(v);
        __nv_bfloat16 lo = __float2bfloat16(v - __bfloat162float(hi));
        int idx = (bN * 8 + (k >> 6)) * IMG_ELEMS + img_off(nloc, k & 63);
        g_W1hi[idx] = hi; g_W1lo[idx] = lo;
    }
    if (tid == 0) g_b1U[q * 4 + gate] = b_ih1[jo] + b_hh1[jo];
}

// proj[tok][q*4+gate] = emb[tok] . W_ih0[row] + b_ih0 + b_hh0  (exact fp32)
__global__ void prep_proj(const float* __restrict__ emb, const float* __restrict__ W_ih0,
                          const float* __restrict__ b_ih0, const float* __restrict__ b_hh0) {
    __shared__ float e[E_DIM];
    int tok = blockIdx.x, tid = threadIdx.x;         // 36 blocks x 256
    if (tid < E_DIM) e[tid] = emb[tok * E_DIM + tid];
    __syncthreads();
    for (int jo = tid; jo < G_DIM; jo += 256) {
        int gate = jo >> 8, q = jo & 255;
        float s = b_ih0[jo] + b_hh0[jo];
        for (int k = 0; k < E_DIM; k++) s += e[k] * W_ih0[jo * E_DIM + k];
        g_projP[tok * G_DIM + q * 4 + gate] = s;
    }
}

__global__ void init_kernel() {
    int i = blockIdx.x * 256 + threadIdx.x;          // NH threads
    __nv_bfloat16 z = __float2bfloat16(0.0f);
    g_h0hi[NH + i] = z; g_h0lo[NH + i] = z;          // buffer 1 = state read at t=0
    g_h1hi[NH + i] = z; g_h1lo[NH + i] = z;
    g_c0[i] = 0.0f; g_c1[i] = 0.0f;
    if (i < N_SEQ) g_acc[i] = 0.0f;
}

__global__ void len_kernel(const int* __restrict__ x) {
    int n = blockIdx.x * 8 + (threadIdx.x >> 5);
    int lane = threadIdx.x & 31;
    int cnt = 0;
    for (int j = lane; j < SEQ_S; j += 32) cnt += (x[n * SEQ_S + j] != 0);
    for (int o = 16; o; o >>= 1) cnt += __shfl_down_sync(0xffffffffu, cnt, o);
    if (lane == 0) g_len[n] = (float)cnt;
}

// ---------------- main: layer0 step tau (CTA 0-255) + layer1 step tau-1 (CTA 256-511) ----------------
// CTA tile M=128 x N=128, 8 warps (warpM 0-3, warpCol 0-1), warp tile 32x64.
// Split-3 bf16 HMMA into fp32 acc; K chunks of 64 double-buffered via cp.async.bulk.
__global__ __launch_bounds__(256)
void lstm_mma(const int* __restrict__ x, int tau) {
    extern __shared__ char smraw[];
    const bool isL1 = (blockIdx.x >= 256);
    if (!isL1 && tau >= T_STEPS) return;
    if (isL1 && tau == 0) return;
    const int t = isL1 ? tau - 1 : tau;
    const int cta = blockIdx.x & 255;
    const int bM = cta >> 3, bN = cta & 7;
    const int NC = isL1 ? 8 : 4;

    unsigned base = smem_u32(smraw);
    unsigned sb = (base + 127u) & ~127u;
    int* tokS = (int*)(smraw + (sb - base) + 2 * STAGE_BYTES + 16);
    unsigned mb0 = sb + 2 * STAGE_BYTES, mb1 = mb0 + 8;

    const int tid = threadIdx.x;
    if (tid == 0) { MBAR_INIT(mb0, 1); MBAR_INIT(mb1, 1); }
    if (!isL1 && tid < 128) tokS[tid] = x[(bM * 128 + tid) * SEQ_S + t];
    __syncthreads();

    const __nv_bfloat16* Whi = isL1 ? (g_W1hi + bN * 8 * IMG_ELEMS) : (g_W0hi + bN * 4 * IMG_ELEMS);
    const __nv_bfloat16* Wlo = isL1 ? (g_W1lo + bN * 8 * IMG_ELEMS) : (g_W0lo + bN * 4 * IMG_ELEMS);

    auto issue = [&](int c, int s) {
        unsigned st = sb + s * STAGE_BYTES;
        const __nv_bfloat16 *ah, *al;
        if (!isL1) {
            size_t o = (size_t)((t + 1) & 1) * NH + (size_t)(c * 32 + bM) * IMG_ELEMS;
            ah = g_h0hi + o; al = g_h0lo + o;
        } else if (c < 4) {
            size_t o = (size_t)(t & 1) * NH + (size_t)(c * 32 + bM) * IMG_ELEMS;
            ah = g_h0hi + o; al = g_h0lo + o;
        } else {
            size_t o = (size_t)((t + 1) & 1) * NH + (size_t)((c - 4) * 32 + bM) * IMG_ELEMS;
            ah = g_h1hi + o; al = g_h1lo + o;
        }
        unsigned mb = s ? mb1 : mb0;
        MBAR_EXPECT(mb, 65536u);
        BULK_G2S(st,          ah,                       16384u, mb);
        BULK_G2S(st + 16384u, al,                       16384u, mb);
        BULK_G2S(st + 32768u, Whi + (size_t)c * IMG_ELEMS, 16384u, mb);
        BULK_G2S(st + 49152u, Wlo + (size_t)c * IMG_ELEMS, 16384u, mb);
    };

    if (tid == 0) { issue(0, 0); issue(1, 1); }

    // per-lane ldmatrix address components
    const int wid = tid >> 5, lane = tid & 31;
    const int wM = wid & 3, wC = wid >> 2;
    const int rA0 = wM * 32 + (lane & 7) + ((lane >> 3) & 1) * 8;   // mi=0 row
    const int rA1 = rA0 + 16;                                        // mi=1 row
    const unsigned khA = (unsigned)(lane >> 4);                      // k half for A
    const unsigned offA0 = rA0 * 128, offA1 = rA1 * 128;
    const unsigned rxA0 = rA0 & 7, rxA1 = rA1 & 7;
    const unsigned khB = (unsigned)((lane >> 3) & 1);                // k half for B
    unsigned offB[4], rxB[4];
#pragma unroll
    for (int p = 0; p < 4; p++) {
        int nB = wC * 64 + (2 * p + ((lane >> 4) & 1)) * 8 + (lane & 7);
        offB[p] = nB * 128; rxB[p] = nB & 7;
    }

    float acc[2][8][4];
#pragma unroll
    for (int mi = 0; mi < 2; mi++)
#pragma unroll
        for (int j = 0; j < 8; j++)
#pragma unroll
            for (int r = 0; r < 4; r++) acc[mi][j][r] = 0.0f;

    for (int c = 0; c < NC; c++) {
        const int s = c & 1;
        mbar_wait(s ? mb1 : mb0, (unsigned)((c >> 1) & 1));
        const unsigned stg = sb + s * STAGE_BYTES;
#pragma unroll
        for (int ks = 0; ks < 4; ks++) {
            const unsigned kb = (unsigned)(ks * 2);
            uint32_t ah0[4], ah1[4], al0[4], al1[4];
            {
                unsigned a0 = stg + offA0 + (((kb + khA) ^ rxA0) << 4);
                unsigned a1 = stg + offA1 + (((kb + khA) ^ rxA1) << 4);
                LDSM4(ah0[0], ah0[1], ah0[2], ah0[3], a0);
                LDSM4(ah1[0], ah1[1], ah1[2], ah1[3], a1);
                LDSM4(al0[0], al0[1], al0[2], al0[3], a0 + 16384u);
                LDSM4(al1[0], al1[1], al1[2], al1[3], a1 + 16384u);
            }
            uint32_t bh[8][2], bl[8][2];
#pragma unroll
            for (int p = 0; p < 4; p++) {
                unsigned ab = stg + 32768u + offB[p] + (((kb + khB) ^ rxB[p]) << 4);
                LDSM4(bh[2 * p][0], bh[2 * p][1], bh[2 * p + 1][0], bh[2 * p + 1][1], ab);
                LDSM4(bl[2 * p][0], bl[2 * p][1], bl[2 * p + 1][0], bl[2 * p + 1][1], ab + 16384u);
            }
#pragma unroll
            for (int j = 0; j < 8; j++) {
                MMA16816(acc[0][j], ah0, bh[j][0], bh[j][1]);
                MMA16816(acc[0][j], ah0, bl[j][0], bl[j][1]);
                MMA16816(acc[0][j], al0, bh[j][0], bh[j][1]);
                MMA16816(acc[1][j], ah1, bh[j][0], bh[j][1]);
                MMA16816(acc[1][j], ah1, bl[j][0], bl[j][1]);
                MMA16816(acc[1][j], al1, bh[j][0], bh[j][1]);
            }
        }
        __syncthreads();
        if (c + 2 < NC && tid == 0) issue(c + 2, s);
    }

    // ---- epilogue: gates (register-local quadruples) -> LSTM pointwise -> swizzled h images ----
    float* cst = isL1 ? g_c1 : g_c0;
    __nv_bfloat16* ohi = (isL1 ? g_h1hi : g_h0hi) + (size_t)(t & 1) * NH;
    __nv_bfloat16* olo = (isL1 ? g_h1lo : g_h0lo) + (size_t)(t & 1) * NH;
    const int gID = lane >> 2, a4 = lane & 3;
#pragma unroll
    for (int mi = 0; mi < 2; mi++) {
#pragma unroll
        for (int rs = 0; rs < 2; rs++) {
            const int rloc = wM * 32 + mi * 16 + gID + rs * 8;
            const int n = bM * 128 + rloc;
            const float* bias4 = isL1 ? g_b1U : (g_projP + (size_t)tokS[rloc] * G_DIM);
#pragma unroll
            for (int jp = 0; jp < 4; jp++) {
                const int q = bN * 32 + wC * 16 + a4 * 4 + jp;
                float4 bb = *(const float4*)&bias4[q * 4];
                float gi = acc[mi][2 * jp][rs * 2 + 0] + bb.x;
                float gf = acc[mi][2 * jp][rs * 2 + 1] + bb.y;
                float gg = acc[mi][2 * jp + 1][rs * 2 + 0] + bb.z;
                float go = acc[mi][2 * jp + 1][rs * 2 + 1] + bb.w;
                size_t ci = (size_t)n * H_DIM + q;
                float ii = fsig(gi), ff = fsig(gf), gv = ftanh(gg), oo = fsig(go);
                float cn = ff * cst[ci] + ii * gv;
                cst[ci] = cn;
                float h = oo * ftanh(cn);
                __nv_bfloat16 hh = __float2bfloat16(h);
                __nv_bfloat16 hl = __float2bfloat16(h - __bfloat162float(hh));
                int off = ((q >> 6) * 32 + bM) * IMG_ELEMS + img_off(rloc, q & 63);
                ohi[off] = hh; olo[off] = hl;
                if (isL1) g_h1f[(size_t)t * NH + ci] = h;
            }
        }
    }
}

// ---------------- fc + relu + log_softmax + probs + masked NLL ----------------
__global__ __launch_bounds__(288)
void fc_kernel(const float* __restrict__ fc_W, const float* __restrict__ fc_b,
               const int* __restrict__ x, float* __restrict__ out) {
    __shared__ float Ws[VOCAB][H_DIM + 1];
    __shared__ float hs[8][H_DIM];
    __shared__ float lg[8][VOCAB + 2];
    __shared__ float lse_s[8];

    const int t = blockIdx.y;
    const int n0 = blockIdx.x * 8;
    const int tid = threadIdx.x;

    for (int i = tid; i < VOCAB * H_DIM; i += 288) Ws[i / H_DIM][i % H_DIM] = fc_W[i];
    const float* hsrc = g_h1f + (size_t)t * NH + (size_t)n0 * H_DIM;
    for (int i = tid; i < 8 * H_DIM; i += 288) hs[i / H_DIM][i % H_DIM] = hsrc[i];
    __syncthreads();

    int s = tid / VOCAB;
    int v = tid - s * VOCAB;
    float a = fc_b[v];
#pragma unroll 8
    for (int k = 0; k < H_DIM; k++) a += hs[s][k] * Ws[v][k];
    float l = fmaxf(a, 0.0f);
    lg[s][v] = l;
    __syncthreads();

    if (v == 0) {
        float m = -1e30f;
        for (int j = 0; j < VOCAB; j++) m = fmaxf(m, lg[s][j]);
        float sum = 0.0f;
        for (int j = 0; j < VOCAB; j++) sum += expf(lg[s][j] - m);
        lse_s[s] = m + logf(sum);
    }
    __syncthreads();

    float lse = lse_s[s];
    int n = n0 + s;
    out[((size_t)n * T_STEPS + t) * VOCAB + v] = expf(l - lse);
    int tgt = x[n * SEQ_S + t + 1];
    if (v == tgt && tgt != 0) atomicAdd(&g_acc[n], lse - l);
}

__global__ void finalize_kernel(float* __restrict__ out) {
    __shared__ float red[1024];
    int tid = threadIdx.x;
    float sum = 0.0f;
    for (int n = tid; n < N_SEQ; n += 1024) {
        float ml = g_acc[n] / g_len[n];
        out[PROBS_OFF + n] = ml;
        sum += ml;
    }
    red[tid] = sum;
    __syncthreads();
    for (int sft = 512; sft > 0; sft >>= 1) {
        if (tid < sft) red[tid] += red[tid + sft];
        __syncthreads();
    }
    if (tid == 0) out[PROBS_OFF + N_SEQ] = red[0] / (float)N_SEQ;
}

// ---------------- launch ----------------
extern "C" void kernel_launch(void* const* d_in, const int* in_sizes, int n_in,
                              void* d_out, int out_size) {
    const int*   x     = (const int*)  d_in[0];
    const float* emb   = (const float*)d_in[1];
    const float* W_ih0 = (const float*)d_in[2];
    const float* W_hh0 = (const float*)d_in[3];
    const float* b_ih0 = (const float*)d_in[4];
    const float* b_hh0 = (const float*)d_in[5];
    const float* W_ih1 = (const float*)d_in[6];
    const float* W_hh1 = (const float*)d_in[7];
    const float* b_ih1 = (const float*)d_in[8];
    const float* b_hh1 = (const float*)d_in[9];
    const float* fc_W  = (const float*)d_in[10];
    const float* fc_b  = (const float*)d_in[11];
    float* out = (float*)d_out;

    cudaFuncSetAttribute(lstm_mma, cudaFuncAttributeMaxDynamicSharedMemorySize, SMEM_SZ);

    prep_w<<<G_DIM, 128>>>(W_hh0, W_ih1, W_hh1, b_ih1, b_hh1);
    prep_proj<<<VOCAB, 256>>>(emb, W_ih0, b_ih0, b_hh0);
    init_kernel<<<NH / 256, 256>>>();
    len_kernel<<<N_SEQ / 8, 256>>>(x);

    for (int tau = 0; tau <= T_STEPS; tau++)
        lstm_mma<<<512, 256, SMEM_SZ>>>(x, tau);

    fc_kernel<<<dim3(N_SEQ / 8, T_STEPS), 288>>>(fc_W, fc_b, x, out);
    finalize_kernel<<<1, 1024>>>(out);
}